// round 13
// baseline (speedup 1.0000x reference)
#include <cuda_runtime.h>
#include <cuda_fp16.h>
#include <cstdint>

#define Nn 256
#define Dd 64
#define Cc 32
#define Rr 16
#define Oo 32

// exp(x - rowmax), fp16, [d][r][n][c]
__device__ __half g_LpH[(size_t)Dd * Rr * Nn * Cc];
__device__ __half g_RpH[(size_t)Dd * Rr * Nn * Cc];
// lmax + rmax, [d][r][n]
__device__ float g_msum[Dd * Rr * Nn];
// log-prob scratch, [d][r][o][n]  (coalesced for the GEMM, transposed later; L2-resident)
__device__ float g_scr[(size_t)Dd * Rr * Oo * Nn];

// ---------------- kernel B: left/right -> rowmax-shifted exp (fp16) ----------------
__global__ __launch_bounds__(128) void prep_kernel(const float* __restrict__ left,
                                                   const float* __restrict__ right) {
    __shared__ float sL[4][Cc * 17], sR[4][Cc * 17];
    __shared__ float lmaxs[4][Rr], rmaxs[4][Rr];
    const int w = threadIdx.x >> 5;
    const int n = blockIdx.x >> 4;
    const int d = (blockIdx.x & 15) * 4 + w;
    const int c = threadIdx.x & 31;
    float lv[Rr], rv[Rr];
    const float4* lp = reinterpret_cast<const float4*>(left + ((size_t)(n * Dd + d) * Cc + c) * Rr);
    const float4* rp = reinterpret_cast<const float4*>(right + ((size_t)(n * Dd + d) * Cc + c) * Rr);
#pragma unroll
    for (int q = 0; q < 4; q++) {
        *reinterpret_cast<float4*>(&lv[q * 4]) = lp[q];
        *reinterpret_cast<float4*>(&rv[q * 4]) = rp[q];
    }
#pragma unroll
    for (int rr = 0; rr < Rr; rr++) { sL[w][c * 17 + rr] = lv[rr]; sR[w][c * 17 + rr] = rv[rr]; }
    __syncwarp();
    if (c < 16) {
        float m = -3.4e38f;
        for (int cc = 0; cc < Cc; cc++) m = fmaxf(m, sL[w][cc * 17 + c]);
        lmaxs[w][c] = m;
    } else {
        const int rr = c - 16;
        float m = -3.4e38f;
        for (int cc = 0; cc < Cc; cc++) m = fmaxf(m, sR[w][cc * 17 + rr]);
        rmaxs[w][rr] = m;
    }
    __syncwarp();
#pragma unroll
    for (int rr = 0; rr < Rr; rr++) {
        const size_t base = ((size_t)(d * Rr + rr) * Nn + n) * Cc + c;
        g_LpH[base] = __float2half_rn(__expf(lv[rr] - lmaxs[w][rr]));
        g_RpH[base] = __float2half_rn(__expf(rv[rr] - rmaxs[w][rr]));
    }
    if (c < 16) g_msum[(d * Rr + c) * Nn + n] = lmaxs[w][c] + rmaxs[w][c];
}

// ---------------- kernel C: warp-MMA batched GEMM, 8 warps x 32n (2x A reuse) ----------------
__device__ __forceinline__ uint32_t s2u(const void* p) {
    uint32_t a;
    asm("{ .reg .u64 t; cvta.to.shared.u64 t, %1; cvt.u32.u64 %0, t; }" : "=r"(a) : "l"(p));
    return a;
}
__device__ __forceinline__ void ldmx4(uint32_t* a, uint32_t addr) {
    asm volatile("ldmatrix.sync.aligned.m8n8.x4.shared.b16 {%0,%1,%2,%3}, [%4];"
                 : "=r"(a[0]), "=r"(a[1]), "=r"(a[2]), "=r"(a[3]) : "r"(addr));
}
__device__ __forceinline__ void mma16816(float* c, const uint32_t* a, uint32_t b0, uint32_t b1) {
    asm volatile(
        "mma.sync.aligned.m16n8k16.row.col.f32.f16.f16.f32 "
        "{%0,%1,%2,%3},{%4,%5,%6,%7},{%8,%9},{%0,%1,%2,%3};"
        : "+f"(c[0]), "+f"(c[1]), "+f"(c[2]), "+f"(c[3])
        : "r"(a[0]), "r"(a[1]), "r"(a[2]), "r"(a[3]), "r"(b0), "r"(b1));
}

#define WSTRIDE 1032   // halves per padded W row (2064 B)
#define LPSTRIDE 40    // halves per padded Lp row (80 B = 16B-aligned, conflict-free reads)
#define SMEM_EINSUM ((32 * WSTRIDE + Nn * LPSTRIDE) * 2)

__global__ __launch_bounds__(256) void einsum_mma_kernel(const float* __restrict__ logits) {
    extern __shared__ __align__(16) __half sm[];
    __half* smW = sm;                      // 32 x WSTRIDE
    __half* sLp = sm + 32 * WSTRIDE;       // Nn x LPSTRIDE
    const int tid = threadIdx.x;
    const int wid = tid >> 5;
    const int ln = tid & 31;
    const int b = blockIdx.x;  // d*16 + r
    const int r = b & 15;
    const int d = b >> 4;

    // ---- stage W: fused softmax of logits[d, o, r, :], 4 o-rows per warp ----
#pragma unroll
    for (int rr2 = 0; rr2 < 4; rr2++) {
        const int o = wid * 4 + rr2;
        const float4* src = reinterpret_cast<const float4*>(
            logits + (((size_t)(d * Oo + o) * Rr + r) << 10));
        float4 v[8];
#pragma unroll
        for (int u = 0; u < 8; u++) v[u] = src[u * 32 + ln];
        float m = -3.4e38f;
#pragma unroll
        for (int u = 0; u < 8; u++)
            m = fmaxf(m, fmaxf(fmaxf(v[u].x, v[u].y), fmaxf(v[u].z, v[u].w)));
#pragma unroll
        for (int t = 16; t; t >>= 1) m = fmaxf(m, __shfl_xor_sync(~0u, m, t));
        float s = 0.f;
#pragma unroll
        for (int u = 0; u < 8; u++) {
            v[u].x = __expf(v[u].x - m);
            v[u].y = __expf(v[u].y - m);
            v[u].z = __expf(v[u].z - m);
            v[u].w = __expf(v[u].w - m);
            s += (v[u].x + v[u].y) + (v[u].z + v[u].w);
        }
#pragma unroll
        for (int t = 16; t; t >>= 1) s += __shfl_xor_sync(~0u, s, t);
        const float inv = 1.0f / s;
#pragma unroll
        for (int u = 0; u < 8; u++) {
            const __half2 h0 = __floats2half2_rn(v[u].x * inv, v[u].y * inv);
            const __half2 h1 = __floats2half2_rn(v[u].z * inv, v[u].w * inv);
            uint2 wv;
            wv.x = *reinterpret_cast<const uint32_t*>(&h0);
            wv.y = *reinterpret_cast<const uint32_t*>(&h1);
            *reinterpret_cast<uint2*>(smW + o * WSTRIDE + (u * 32 + ln) * 4) = wv;
        }
    }

    // ---- stage Lp into padded smem: one n per thread (80B rows, 16B-aligned) ----
    {
        const uint4* src = reinterpret_cast<const uint4*>(g_LpH + ((size_t)b * Nn + tid) * Cc);
#pragma unroll
        for (int q = 0; q < 4; q++)
            *reinterpret_cast<uint4*>(sLp + tid * LPSTRIDE + q * 8) = src[q];
    }

    // ---- per-lane Rp operands: 4 n-tiles of 8 ----
    const int wb = wid * 32;
    int nn[4];
    __half2 rp[4][4];
#pragma unroll
    for (int nt = 0; nt < 4; nt++) {
        nn[nt] = wb + nt * 8 + (ln >> 2);
        const __half* rsrc = g_RpH + ((size_t)b * Nn + nn[nt]) * Cc + (ln & 3) * 2;
#pragma unroll
        for (int q = 0; q < 4; q++)
            rp[nt][q] = *reinterpret_cast<const __half2*>(rsrc + q * 8);
    }
    __syncthreads();

    float acc[2][4][4];
#pragma unroll
    for (int mt = 0; mt < 2; mt++)
#pragma unroll
        for (int nt = 0; nt < 4; nt++)
#pragma unroll
            for (int q = 0; q < 4; q++) acc[mt][nt][q] = 0.f;

    const uint32_t abase = s2u(smW) + ((uint32_t)(ln & 15) * WSTRIDE + (uint32_t)((ln >> 4) & 1) * 8) * 2;

    __half2 lph2[4];
#pragma unroll 8
    for (int kc = 0; kc < 64; kc++) {  // k16-tile: i = kc>>1, j0 = (kc&1)*16
        if ((kc & 3) == 0) {
#pragma unroll
            for (int nt = 0; nt < 4; nt++)
                lph2[nt] = *reinterpret_cast<const __half2*>(sLp + nn[nt] * LPSTRIDE + (kc >> 1));
        }
        uint32_t a0[4], a1[4];
        ldmx4(a0, abase + (uint32_t)kc * 32);
        ldmx4(a1, abase + 16u * WSTRIDE * 2u + (uint32_t)kc * 32);
        const int q0 = (kc & 1) * 2;
#pragma unroll
        for (int nt = 0; nt < 4; nt++) {
            const __half h = ((kc >> 1) & 1) ? __high2half(lph2[nt]) : __low2half(lph2[nt]);
            const __half2 l2 = __half2half2(h);
            const __half2 b0 = __hmul2(rp[nt][q0], l2);
            const __half2 b1 = __hmul2(rp[nt][q0 + 1], l2);
            const uint32_t u0 = *reinterpret_cast<const uint32_t*>(&b0);
            const uint32_t u1 = *reinterpret_cast<const uint32_t*>(&b1);
            mma16816(acc[0][nt], a0, u0, u1);
            mma16816(acc[1][nt], a1, u0, u1);
        }
    }

    // ---- epilogue: log + msum, write scratch [b][o][n] (n-coalesced) ----
#pragma unroll
    for (int mt = 0; mt < 2; mt++)
#pragma unroll
        for (int nt = 0; nt < 4; nt++) {
            const int o = mt * 16 + (ln >> 2);
            const int n = wb + nt * 8 + (ln & 3) * 2;
            const float2 ms = *reinterpret_cast<const float2*>(&g_msum[b * Nn + n]);
            float2 v0, v1;
            v0.x = __logf(acc[mt][nt][0]) + ms.x;
            v0.y = __logf(acc[mt][nt][1]) + ms.y;
            v1.x = __logf(acc[mt][nt][2]) + ms.x;
            v1.y = __logf(acc[mt][nt][3]) + ms.y;
            float* p = g_scr + ((size_t)b * Oo + o) * Nn + n;
            *reinterpret_cast<float2*>(p) = v0;
            *reinterpret_cast<float2*>(p + 8 * Nn) = v1;
        }
}

// ---------------- kernel D: transpose scratch [d][r][o][n] -> out [n][d][o][r] ----------------
__global__ __launch_bounds__(256) void transpose_kernel(float* __restrict__ out) {
    __shared__ __align__(16) float tile[512 * 17];  // idx = o*16+r, 16 n per CTA
    const int d = blockIdx.x >> 4;
    const int nb = blockIdx.x & 15;
    const int tid = threadIdx.x;
#pragma unroll
    for (int it = 0; it < 8; it++) {
        const int gidx = it * 256 + tid;          // 0..2047
        const int ro = gidx >> 2, s4 = gidx & 3;  // ro = r*32+o
        const float4 v = *reinterpret_cast<const float4*>(
            g_scr + ((size_t)(d * 512 + ro)) * Nn + nb * 16 + s4 * 4);
        const int idx = (ro & 31) * 16 + (ro >> 5);  // o*16 + r
        float* t = &tile[idx * 17 + s4 * 4];
        t[0] = v.x; t[1] = v.y; t[2] = v.z; t[3] = v.w;
    }
    __syncthreads();
#pragma unroll
    for (int n = 0; n < 16; n++) {
        float* ob = out + ((size_t)(nb * 16 + n) * Dd + d) * 512;
        ob[tid] = tile[tid * 17 + n];
        ob[tid + 256] = tile[(tid + 256) * 17 + n];
    }
}

extern "C" void kernel_launch(void* const* d_in, const int* in_sizes, int n_in,
                              void* d_out, int out_size) {
    const float* left = (const float*)d_in[0];
    const float* right = (const float*)d_in[1];
    const float* logits = (const float*)d_in[2];
    float* out = (float*)d_out;

    prep_kernel<<<Nn * Dd / 4, 128>>>(left, right);
    cudaFuncSetAttribute(einsum_mma_kernel, cudaFuncAttributeMaxDynamicSharedMemorySize, SMEM_EINSUM);
    einsum_mma_kernel<<<Dd * Rr, 256, SMEM_EINSUM>>>(logits);
    transpose_kernel<<<Dd * 16, 256>>>(out);
}

// round 14
// speedup vs baseline: 1.0062x; 1.0062x over previous
#include <cuda_runtime.h>
#include <cuda_fp16.h>
#include <cstdint>

#define Nn 256
#define Dd 64
#define Cc 32
#define Rr 16
#define Oo 32

// exp(x - rowmax), fp16, [d][r][n][c]
__device__ __half g_LpH[(size_t)Dd * Rr * Nn * Cc];
__device__ __half g_RpH[(size_t)Dd * Rr * Nn * Cc];
// lmax + rmax, [d][r][n]
__device__ float g_msum[Dd * Rr * Nn];
// log-prob scratch, [d][r][o][n]  (coalesced for the GEMM, transposed later; L2-resident)
__device__ float g_scr[(size_t)Dd * Rr * Oo * Nn];

// ---------------- kernel B: left/right -> rowmax-shifted exp (fp16) ----------------
__global__ __launch_bounds__(128) void prep_kernel(const float* __restrict__ left,
                                                   const float* __restrict__ right) {
    __shared__ float sL[4][Cc * 17], sR[4][Cc * 17];
    __shared__ float lmaxs[4][Rr], rmaxs[4][Rr];
    const int w = threadIdx.x >> 5;
    const int n = blockIdx.x >> 4;
    const int d = (blockIdx.x & 15) * 4 + w;
    const int c = threadIdx.x & 31;
    float lv[Rr], rv[Rr];
    const float4* lp = reinterpret_cast<const float4*>(left + ((size_t)(n * Dd + d) * Cc + c) * Rr);
    const float4* rp = reinterpret_cast<const float4*>(right + ((size_t)(n * Dd + d) * Cc + c) * Rr);
#pragma unroll
    for (int q = 0; q < 4; q++) {
        *reinterpret_cast<float4*>(&lv[q * 4]) = lp[q];
        *reinterpret_cast<float4*>(&rv[q * 4]) = rp[q];
    }
#pragma unroll
    for (int rr = 0; rr < Rr; rr++) { sL[w][c * 17 + rr] = lv[rr]; sR[w][c * 17 + rr] = rv[rr]; }
    __syncwarp();
    if (c < 16) {
        float m = -3.4e38f;
        for (int cc = 0; cc < Cc; cc++) m = fmaxf(m, sL[w][cc * 17 + c]);
        lmaxs[w][c] = m;
    } else {
        const int rr = c - 16;
        float m = -3.4e38f;
        for (int cc = 0; cc < Cc; cc++) m = fmaxf(m, sR[w][cc * 17 + rr]);
        rmaxs[w][rr] = m;
    }
    __syncwarp();
#pragma unroll
    for (int rr = 0; rr < Rr; rr++) {
        const size_t base = ((size_t)(d * Rr + rr) * Nn + n) * Cc + c;
        g_LpH[base] = __float2half_rn(__expf(lv[rr] - lmaxs[w][rr]));
        g_RpH[base] = __float2half_rn(__expf(rv[rr] - rmaxs[w][rr]));
    }
    if (c < 16) g_msum[(d * Rr + c) * Nn + n] = lmaxs[w][c] + rmaxs[w][c];
}

// ---------------- kernel C: warp-MMA batched GEMM, 8 warps x 32n (2x A reuse) ----------------
__device__ __forceinline__ uint32_t s2u(const void* p) {
    uint32_t a;
    asm("{ .reg .u64 t; cvta.to.shared.u64 t, %1; cvt.u32.u64 %0, t; }" : "=r"(a) : "l"(p));
    return a;
}
__device__ __forceinline__ void ldmx4(uint32_t* a, uint32_t addr) {
    asm volatile("ldmatrix.sync.aligned.m8n8.x4.shared.b16 {%0,%1,%2,%3}, [%4];"
                 : "=r"(a[0]), "=r"(a[1]), "=r"(a[2]), "=r"(a[3]) : "r"(addr));
}
__device__ __forceinline__ void mma16816(float* c, const uint32_t* a, uint32_t b0, uint32_t b1) {
    asm volatile(
        "mma.sync.aligned.m16n8k16.row.col.f32.f16.f16.f32 "
        "{%0,%1,%2,%3},{%4,%5,%6,%7},{%8,%9},{%0,%1,%2,%3};"
        : "+f"(c[0]), "+f"(c[1]), "+f"(c[2]), "+f"(c[3])
        : "r"(a[0]), "r"(a[1]), "r"(a[2]), "r"(a[3]), "r"(b0), "r"(b1));
}

#define WSTRIDE 1032   // halves per padded W row (2064 B)
#define LPSTRIDE 40    // halves per padded Lp row (80 B = 16B-aligned, conflict-free reads)
#define SMEM_EINSUM ((32 * WSTRIDE + Nn * LPSTRIDE) * 2)

__global__ __launch_bounds__(256) void einsum_mma_kernel(const float* __restrict__ logits) {
    extern __shared__ __align__(16) __half sm[];
    __half* smW = sm;                      // 32 x WSTRIDE
    __half* sLp = sm + 32 * WSTRIDE;       // Nn x LPSTRIDE
    const int tid = threadIdx.x;
    const int wid = tid >> 5;
    const int ln = tid & 31;
    const int b = blockIdx.x;  // d*16 + r
    const int r = b & 15;
    const int d = b >> 4;

    // ---- stage W: fused softmax of logits[d, o, r, :], 4 o-rows per warp ----
#pragma unroll
    for (int rr2 = 0; rr2 < 4; rr2++) {
        const int o = wid * 4 + rr2;
        const float4* src = reinterpret_cast<const float4*>(
            logits + (((size_t)(d * Oo + o) * Rr + r) << 10));
        float4 v[8];
#pragma unroll
        for (int u = 0; u < 8; u++) v[u] = src[u * 32 + ln];
        float m = -3.4e38f;
#pragma unroll
        for (int u = 0; u < 8; u++)
            m = fmaxf(m, fmaxf(fmaxf(v[u].x, v[u].y), fmaxf(v[u].z, v[u].w)));
#pragma unroll
        for (int t = 16; t; t >>= 1) m = fmaxf(m, __shfl_xor_sync(~0u, m, t));
        float s = 0.f;
#pragma unroll
        for (int u = 0; u < 8; u++) {
            v[u].x = __expf(v[u].x - m);
            v[u].y = __expf(v[u].y - m);
            v[u].z = __expf(v[u].z - m);
            v[u].w = __expf(v[u].w - m);
            s += (v[u].x + v[u].y) + (v[u].z + v[u].w);
        }
#pragma unroll
        for (int t = 16; t; t >>= 1) s += __shfl_xor_sync(~0u, s, t);
        const float inv = 1.0f / s;
#pragma unroll
        for (int u = 0; u < 8; u++) {
            const __half2 h0 = __floats2half2_rn(v[u].x * inv, v[u].y * inv);
            const __half2 h1 = __floats2half2_rn(v[u].z * inv, v[u].w * inv);
            uint2 wv;
            wv.x = *reinterpret_cast<const uint32_t*>(&h0);
            wv.y = *reinterpret_cast<const uint32_t*>(&h1);
            *reinterpret_cast<uint2*>(smW + o * WSTRIDE + (u * 32 + ln) * 4) = wv;
        }
    }

    // ---- stage Lp into padded smem: one n per thread (80B rows, 16B-aligned) ----
    {
        const uint4* src = reinterpret_cast<const uint4*>(g_LpH + ((size_t)b * Nn + tid) * Cc);
#pragma unroll
        for (int q = 0; q < 4; q++)
            *reinterpret_cast<uint4*>(sLp + tid * LPSTRIDE + q * 8) = src[q];
    }

    // ---- per-lane Rp operands: 4 n-tiles of 8 ----
    const int wb = wid * 32;
    int nn[4];
    __half2 rp[4][4];
#pragma unroll
    for (int nt = 0; nt < 4; nt++) {
        nn[nt] = wb + nt * 8 + (ln >> 2);
        const __half* rsrc = g_RpH + ((size_t)b * Nn + nn[nt]) * Cc + (ln & 3) * 2;
#pragma unroll
        for (int q = 0; q < 4; q++)
            rp[nt][q] = *reinterpret_cast<const __half2*>(rsrc + q * 8);
    }
    __syncthreads();

    float acc[2][4][4];
#pragma unroll
    for (int mt = 0; mt < 2; mt++)
#pragma unroll
        for (int nt = 0; nt < 4; nt++)
#pragma unroll
            for (int q = 0; q < 4; q++) acc[mt][nt][q] = 0.f;

    const uint32_t abase = s2u(smW) + ((uint32_t)(ln & 15) * WSTRIDE + (uint32_t)((ln >> 4) & 1) * 8) * 2;

    __half2 lph2[4];
#pragma unroll 8
    for (int kc = 0; kc < 64; kc++) {  // k16-tile: i = kc>>1, j0 = (kc&1)*16
        if ((kc & 3) == 0) {
#pragma unroll
            for (int nt = 0; nt < 4; nt++)
                lph2[nt] = *reinterpret_cast<const __half2*>(sLp + nn[nt] * LPSTRIDE + (kc >> 1));
        }
        uint32_t a0[4], a1[4];
        ldmx4(a0, abase + (uint32_t)kc * 32);
        ldmx4(a1, abase + 16u * WSTRIDE * 2u + (uint32_t)kc * 32);
        const int q0 = (kc & 1) * 2;
#pragma unroll
        for (int nt = 0; nt < 4; nt++) {
            const __half h = ((kc >> 1) & 1) ? __high2half(lph2[nt]) : __low2half(lph2[nt]);
            const __half2 l2 = __half2half2(h);
            const __half2 b0 = __hmul2(rp[nt][q0], l2);
            const __half2 b1 = __hmul2(rp[nt][q0 + 1], l2);
            const uint32_t u0 = *reinterpret_cast<const uint32_t*>(&b0);
            const uint32_t u1 = *reinterpret_cast<const uint32_t*>(&b1);
            mma16816(acc[0][nt], a0, u0, u1);
            mma16816(acc[1][nt], a1, u0, u1);
        }
    }

    // ---- epilogue: log + msum, write scratch [b][o][n] (n-coalesced) ----
#pragma unroll
    for (int mt = 0; mt < 2; mt++)
#pragma unroll
        for (int nt = 0; nt < 4; nt++) {
            const int o = mt * 16 + (ln >> 2);
            const int n = wb + nt * 8 + (ln & 3) * 2;
            const float2 ms = *reinterpret_cast<const float2*>(&g_msum[b * Nn + n]);
            float2 v0, v1;
            v0.x = __logf(acc[mt][nt][0]) + ms.x;
            v0.y = __logf(acc[mt][nt][1]) + ms.y;
            v1.x = __logf(acc[mt][nt][2]) + ms.x;
            v1.y = __logf(acc[mt][nt][3]) + ms.y;
            float* p = g_scr + ((size_t)b * Oo + o) * Nn + n;
            *reinterpret_cast<float2*>(p) = v0;
            *reinterpret_cast<float2*>(p + 8 * Nn) = v1;
        }
}

// ---------------- kernel D: transpose scratch [d][r][o][n] -> out [n][d][o][r] ----------------
__global__ __launch_bounds__(256) void transpose_kernel(float* __restrict__ out) {
    __shared__ __align__(16) float tile[512 * 17];  // idx = o*16+r, 16 n per CTA
    const int d = blockIdx.x >> 4;
    const int nb = blockIdx.x & 15;
    const int tid = threadIdx.x;
#pragma unroll
    for (int it = 0; it < 8; it++) {
        const int gidx = it * 256 + tid;          // 0..2047
        const int ro = gidx >> 2, s4 = gidx & 3;  // ro = r*32+o
        const float4 v = *reinterpret_cast<const float4*>(
            g_scr + ((size_t)(d * 512 + ro)) * Nn + nb * 16 + s4 * 4);
        const int idx = (ro & 31) * 16 + (ro >> 5);  // o*16 + r
        float* t = &tile[idx * 17 + s4 * 4];
        t[0] = v.x; t[1] = v.y; t[2] = v.z; t[3] = v.w;
    }
    __syncthreads();
#pragma unroll
    for (int n = 0; n < 16; n++) {
        float* ob = out + ((size_t)(nb * 16 + n) * Dd + d) * 512;
        ob[tid] = tile[tid * 17 + n];
        ob[tid + 256] = tile[(tid + 256) * 17 + n];
    }
}

extern "C" void kernel_launch(void* const* d_in, const int* in_sizes, int n_in,
                              void* d_out, int out_size) {
    const float* left = (const float*)d_in[0];
    const float* right = (const float*)d_in[1];
    const float* logits = (const float*)d_in[2];
    float* out = (float*)d_out;

    prep_kernel<<<Nn * Dd / 4, 128>>>(left, right);
    cudaFuncSetAttribute(einsum_mma_kernel, cudaFuncAttributeMaxDynamicSharedMemorySize, SMEM_EINSUM);
    einsum_mma_kernel<<<Dd * Rr, 256, SMEM_EINSUM>>>(logits);
    transpose_kernel<<<Dd * 16, 256>>>(out);
}

// round 15
// speedup vs baseline: 1.0065x; 1.0003x over previous
#include <cuda_runtime.h>
#include <cuda_fp16.h>
#include <cstdint>

#define Nn 256
#define Dd 64
#define Cc 32
#define Rr 16
#define Oo 32

// exp(x - rowmax), fp16, [d][r][n][c]
__device__ __half g_LpH[(size_t)Dd * Rr * Nn * Cc];
__device__ __half g_RpH[(size_t)Dd * Rr * Nn * Cc];
// lmax + rmax, [d][r][n]
__device__ float g_msum[Dd * Rr * Nn];
// log-prob scratch, [d][r][o][n]  (coalesced for the GEMM, transposed later; L2-resident)
__device__ float g_scr[(size_t)Dd * Rr * Oo * Nn];

// ---------------- kernel B: left/right -> rowmax-shifted exp (fp16) ----------------
__global__ __launch_bounds__(128) void prep_kernel(const float* __restrict__ left,
                                                   const float* __restrict__ right) {
    __shared__ float sL[4][Cc * 17], sR[4][Cc * 17];
    __shared__ float lmaxs[4][Rr], rmaxs[4][Rr];
    const int w = threadIdx.x >> 5;
    const int n = blockIdx.x >> 4;
    const int d = (blockIdx.x & 15) * 4 + w;
    const int c = threadIdx.x & 31;
    float lv[Rr], rv[Rr];
    const float4* lp = reinterpret_cast<const float4*>(left + ((size_t)(n * Dd + d) * Cc + c) * Rr);
    const float4* rp = reinterpret_cast<const float4*>(right + ((size_t)(n * Dd + d) * Cc + c) * Rr);
#pragma unroll
    for (int q = 0; q < 4; q++) {
        *reinterpret_cast<float4*>(&lv[q * 4]) = lp[q];
        *reinterpret_cast<float4*>(&rv[q * 4]) = rp[q];
    }
#pragma unroll
    for (int rr = 0; rr < Rr; rr++) { sL[w][c * 17 + rr] = lv[rr]; sR[w][c * 17 + rr] = rv[rr]; }
    __syncwarp();
    if (c < 16) {
        float m = -3.4e38f;
        for (int cc = 0; cc < Cc; cc++) m = fmaxf(m, sL[w][cc * 17 + c]);
        lmaxs[w][c] = m;
    } else {
        const int rr = c - 16;
        float m = -3.4e38f;
        for (int cc = 0; cc < Cc; cc++) m = fmaxf(m, sR[w][cc * 17 + rr]);
        rmaxs[w][rr] = m;
    }
    __syncwarp();
#pragma unroll
    for (int rr = 0; rr < Rr; rr++) {
        const size_t base = ((size_t)(d * Rr + rr) * Nn + n) * Cc + c;
        g_LpH[base] = __float2half_rn(__expf(lv[rr] - lmaxs[w][rr]));
        g_RpH[base] = __float2half_rn(__expf(rv[rr] - rmaxs[w][rr]));
    }
    if (c < 16) g_msum[(d * Rr + c) * Nn + n] = lmaxs[w][c] + rmaxs[w][c];
}

// ---------------- kernel C: warp-MMA batched GEMM, 8 warps x 32n (2x A reuse) ----------------
__device__ __forceinline__ uint32_t s2u(const void* p) {
    uint32_t a;
    asm("{ .reg .u64 t; cvta.to.shared.u64 t, %1; cvt.u32.u64 %0, t; }" : "=r"(a) : "l"(p));
    return a;
}
__device__ __forceinline__ void ldmx4(uint32_t* a, uint32_t addr) {
    asm volatile("ldmatrix.sync.aligned.m8n8.x4.shared.b16 {%0,%1,%2,%3}, [%4];"
                 : "=r"(a[0]), "=r"(a[1]), "=r"(a[2]), "=r"(a[3]) : "r"(addr));
}
__device__ __forceinline__ void mma16816(float* c, const uint32_t* a, uint32_t b0, uint32_t b1) {
    asm volatile(
        "mma.sync.aligned.m16n8k16.row.col.f32.f16.f16.f32 "
        "{%0,%1,%2,%3},{%4,%5,%6,%7},{%8,%9},{%0,%1,%2,%3};"
        : "+f"(c[0]), "+f"(c[1]), "+f"(c[2]), "+f"(c[3])
        : "r"(a[0]), "r"(a[1]), "r"(a[2]), "r"(a[3]), "r"(b0), "r"(b1));
}

#define WSTRIDE 1032   // halves per padded W row (2064 B)
#define LPSTRIDE 40    // halves per padded Lp row (80 B = 16B-aligned, conflict-free reads)
#define SMEM_EINSUM ((32 * WSTRIDE + Nn * LPSTRIDE) * 2)

__global__ __launch_bounds__(256) void einsum_mma_kernel(const float* __restrict__ logits) {
    extern __shared__ __align__(16) __half sm[];
    __half* smW = sm;                      // 32 x WSTRIDE
    __half* sLp = sm + 32 * WSTRIDE;       // Nn x LPSTRIDE
    const int tid = threadIdx.x;
    const int wid = tid >> 5;
    const int ln = tid & 31;
    const int b = blockIdx.x;  // d*16 + r
    const int r = b & 15;
    const int d = b >> 4;

    // ---- stage W: fused softmax of logits[d, o, r, :], 4 o-rows per warp ----
#pragma unroll
    for (int rr2 = 0; rr2 < 4; rr2++) {
        const int o = wid * 4 + rr2;
        const float4* src = reinterpret_cast<const float4*>(
            logits + (((size_t)(d * Oo + o) * Rr + r) << 10));
        float4 v[8];
#pragma unroll
        for (int u = 0; u < 8; u++) v[u] = src[u * 32 + ln];
        float m = -3.4e38f;
#pragma unroll
        for (int u = 0; u < 8; u++)
            m = fmaxf(m, fmaxf(fmaxf(v[u].x, v[u].y), fmaxf(v[u].z, v[u].w)));
#pragma unroll
        for (int t = 16; t; t >>= 1) m = fmaxf(m, __shfl_xor_sync(~0u, m, t));
        float s = 0.f;
#pragma unroll
        for (int u = 0; u < 8; u++) {
            v[u].x = __expf(v[u].x - m);
            v[u].y = __expf(v[u].y - m);
            v[u].z = __expf(v[u].z - m);
            v[u].w = __expf(v[u].w - m);
            s += (v[u].x + v[u].y) + (v[u].z + v[u].w);
        }
#pragma unroll
        for (int t = 16; t; t >>= 1) s += __shfl_xor_sync(~0u, s, t);
        const float inv = 1.0f / s;
#pragma unroll
        for (int u = 0; u < 8; u++) {
            const __half2 h0 = __floats2half2_rn(v[u].x * inv, v[u].y * inv);
            const __half2 h1 = __floats2half2_rn(v[u].z * inv, v[u].w * inv);
            uint2 wv;
            wv.x = *reinterpret_cast<const uint32_t*>(&h0);
            wv.y = *reinterpret_cast<const uint32_t*>(&h1);
            *reinterpret_cast<uint2*>(smW + o * WSTRIDE + (u * 32 + ln) * 4) = wv;
        }
    }

    // ---- stage Lp into padded smem: one n per thread (80B rows, 16B-aligned) ----
    {
        const uint4* src = reinterpret_cast<const uint4*>(g_LpH + ((size_t)b * Nn + tid) * Cc);
#pragma unroll
        for (int q = 0; q < 4; q++)
            *reinterpret_cast<uint4*>(sLp + tid * LPSTRIDE + q * 8) = src[q];
    }

    // ---- per-lane Rp operands: 4 n-tiles of 8 ----
    const int wb = wid * 32;
    int nn[4];
    __half2 rp[4][4];
#pragma unroll
    for (int nt = 0; nt < 4; nt++) {
        nn[nt] = wb + nt * 8 + (ln >> 2);
        const __half* rsrc = g_RpH + ((size_t)b * Nn + nn[nt]) * Cc + (ln & 3) * 2;
#pragma unroll
        for (int q = 0; q < 4; q++)
            rp[nt][q] = *reinterpret_cast<const __half2*>(rsrc + q * 8);
    }
    __syncthreads();

    float acc[2][4][4];
#pragma unroll
    for (int mt = 0; mt < 2; mt++)
#pragma unroll
        for (int nt = 0; nt < 4; nt++)
#pragma unroll
            for (int q = 0; q < 4; q++) acc[mt][nt][q] = 0.f;

    const uint32_t abase = s2u(smW) + ((uint32_t)(ln & 15) * WSTRIDE + (uint32_t)((ln >> 4) & 1) * 8) * 2;

    __half2 lph2[4];
#pragma unroll 8
    for (int kc = 0; kc < 64; kc++) {  // k16-tile: i = kc>>1, j0 = (kc&1)*16
        if ((kc & 3) == 0) {
#pragma unroll
            for (int nt = 0; nt < 4; nt++)
                lph2[nt] = *reinterpret_cast<const __half2*>(sLp + nn[nt] * LPSTRIDE + (kc >> 1));
        }
        uint32_t a0[4], a1[4];
        ldmx4(a0, abase + (uint32_t)kc * 32);
        ldmx4(a1, abase + 16u * WSTRIDE * 2u + (uint32_t)kc * 32);
        const int q0 = (kc & 1) * 2;
#pragma unroll
        for (int nt = 0; nt < 4; nt++) {
            const __half h = ((kc >> 1) & 1) ? __high2half(lph2[nt]) : __low2half(lph2[nt]);
            const __half2 l2 = __half2half2(h);
            const __half2 b0 = __hmul2(rp[nt][q0], l2);
            const __half2 b1 = __hmul2(rp[nt][q0 + 1], l2);
            const uint32_t u0 = *reinterpret_cast<const uint32_t*>(&b0);
            const uint32_t u1 = *reinterpret_cast<const uint32_t*>(&b1);
            mma16816(acc[0][nt], a0, u0, u1);
            mma16816(acc[1][nt], a1, u0, u1);
        }
    }

    // ---- epilogue: log + msum, write scratch [b][o][n] (n-coalesced) ----
#pragma unroll
    for (int mt = 0; mt < 2; mt++)
#pragma unroll
        for (int nt = 0; nt < 4; nt++) {
            const int o = mt * 16 + (ln >> 2);
            const int n = wb + nt * 8 + (ln & 3) * 2;
            const float2 ms = *reinterpret_cast<const float2*>(&g_msum[b * Nn + n]);
            float2 v0, v1;
            v0.x = __logf(acc[mt][nt][0]) + ms.x;
            v0.y = __logf(acc[mt][nt][1]) + ms.y;
            v1.x = __logf(acc[mt][nt][2]) + ms.x;
            v1.y = __logf(acc[mt][nt][3]) + ms.y;
            float* p = g_scr + ((size_t)b * Oo + o) * Nn + n;
            *reinterpret_cast<float2*>(p) = v0;
            *reinterpret_cast<float2*>(p + 8 * Nn) = v1;
        }
}

// ---------------- kernel D: transpose scratch [d][r][o][n] -> out [n][d][o][r] ----------------
__global__ __launch_bounds__(256) void transpose_kernel(float* __restrict__ out) {
    __shared__ __align__(16) float tile[512 * 17];  // idx = o*16+r, 16 n per CTA
    const int d = blockIdx.x >> 4;
    const int nb = blockIdx.x & 15;
    const int tid = threadIdx.x;
#pragma unroll
    for (int it = 0; it < 8; it++) {
        const int gidx = it * 256 + tid;          // 0..2047
        const int ro = gidx >> 2, s4 = gidx & 3;  // ro = r*32+o
        const float4 v = *reinterpret_cast<const float4*>(
            g_scr + ((size_t)(d * 512 + ro)) * Nn + nb * 16 + s4 * 4);
        const int idx = (ro & 31) * 16 + (ro >> 5);  // o*16 + r
        float* t = &tile[idx * 17 + s4 * 4];
        t[0] = v.x; t[1] = v.y; t[2] = v.z; t[3] = v.w;
    }
    __syncthreads();
#pragma unroll
    for (int n = 0; n < 16; n++) {
        float* ob = out + ((size_t)(nb * 16 + n) * Dd + d) * 512;
        ob[tid] = tile[tid * 17 + n];
        ob[tid + 256] = tile[(tid + 256) * 17 + n];
    }
}

extern "C" void kernel_launch(void* const* d_in, const int* in_sizes, int n_in,
                              void* d_out, int out_size) {
    const float* left = (const float*)d_in[0];
    const float* right = (const float*)d_in[1];
    const float* logits = (const float*)d_in[2];
    float* out = (float*)d_out;

    prep_kernel<<<Nn * Dd / 4, 128>>>(left, right);
    cudaFuncSetAttribute(einsum_mma_kernel, cudaFuncAttributeMaxDynamicSharedMemorySize, SMEM_EINSUM);
    einsum_mma_kernel<<<Dd * Rr, 256, SMEM_EINSUM>>>(logits);
    transpose_kernel<<<Dd * 16, 256>>>(out);
}